// round 3
// baseline (speedup 1.0000x reference)
#include <cuda_runtime.h>
#include <cuda_bf16.h>

// ---------------- problem constants ----------------
#define NNN     16384
#define MODIN   113
#define MODOUT  57

typedef unsigned long long u64;

// output layout (float offsets): readout | h_new | msg | hebbian
#define OUT_H    16384
#define OUT_MSG  (OUT_H + 4194304)
#define OUT_HEB  (OUT_MSG + 4194304)

__device__ __forceinline__ u64 pk2(float w) {
    u64 r; asm("mov.b64 %0, {%1, %1};" : "=l"(r) : "f"(w)); return r;
}
__device__ __forceinline__ void fma2(u64 &a, u64 b, u64 c) {
    asm("fma.rn.f32x2 %0, %1, %2, %0;" : "+l"(a) : "l"(b), "l"(c));
}
__device__ __forceinline__ float mytanh(float x) {
    float e = __expf(2.0f * x);
    return 1.0f - __fdividef(2.0f, e + 1.0f);
}
__device__ __forceinline__ float sigm(float x) {
    return __fdividef(1.0f, 1.0f + __expf(-x));
}

// ---------------- kernel A smem layout (float offsets) ----------------
#define OFF_SW1   0        // 64 x 97
#define OFF_SW2   6208     // 32 x 65 (pad)
#define OFF_MW1   8288     // 64 x 97 (96 used)
#define OFF_MW2   14496    // 32 x 65 (pad)
#define OFF_SB1   16576
#define OFF_SB2   16640
#define OFF_MB1   16672
#define OFF_MB2   16736
#define OFF_W1S   16768    // 32 x 113 per-neuron mod_w1
#define OFF_W2S   20384    // 32 x 57 per-neuron mod_w2 ([h][o])
#define OFF_MB1S  22208    // 32
#define OFF_MB2S  22240    // 57 (pad 64)
#define OFF_XIN   22304    // 113 x 8 batch-major mod input
#define OFF_HID   23208    // 32 x 8
#define OFF_OUTS  23464    // 57 x 8
#define OFF_SINT  23920    // 97 x 8
#define OFF_MINT  24696    // 96 x 8
#define OFF_SHST  25464    // 64 x 8
#define OFF_PSUM  25976    // 8 x 32 x 8
#define OFF_ACT   28024    // 200 sigmoids of OUTS[0:200]
#define OFF_CIDX  28224    // 16 ints
#define OFF_BIDX  28240    // 8 ints
#define SMEM_FLOATS 28248
#define SMEM_BYTES  (SMEM_FLOATS*4)

#define GRID_A 296

// partial GEMV: lane owns one output row (W element i at W[i*iStride]),
// accumulates all 8 batches packed as 4 f32x2, for i in [kbeg,kend)
__device__ __forceinline__ void gemv_part(const float* __restrict__ W, int iStride,
                                          const float* __restrict__ X,
                                          float* __restrict__ ps,
                                          int kbeg, int kend)
{
    u64 a0 = 0, a1 = 0, a2 = 0, a3 = 0;
    const float* w = W + kbeg * iStride;
    const u64* x = (const u64*)(X + kbeg * 8);
#pragma unroll 4
    for (int i = kbeg; i < kend; ++i) {
        u64 wp = pk2(*w); w += iStride;
        fma2(a0, wp, x[0]); fma2(a1, wp, x[1]);
        fma2(a2, wp, x[2]); fma2(a3, wp, x[3]);
        x += 4;
    }
    u64* pp = (u64*)ps;
    pp[0] = a0; pp[1] = a1; pp[2] = a2; pp[3] = a3;
}

__global__ void __launch_bounds__(256, 2)
cellA_kernel(const float* __restrict__ ccs,
             const float* __restrict__ hin,
             const float* __restrict__ pm,
             const float* __restrict__ dlog,
             const float* __restrict__ prim,
             const float* __restrict__ trc,
             const float* __restrict__ sw1g, const float* __restrict__ sb1g,
             const float* __restrict__ sw2g, const float* __restrict__ sb2g,
             const float* __restrict__ mw1g, const float* __restrict__ mb1g,
             const float* __restrict__ mw2g, const float* __restrict__ mb2g,
             const float* __restrict__ modw1, const float* __restrict__ modb1g,
             const float* __restrict__ modw2, const float* __restrict__ modb2g,
             const float* __restrict__ nidg,
             const int*   __restrict__ conn,
             const int*   __restrict__ bconn,
             float* __restrict__ outp)
{
    extern __shared__ float smf[];
    const int tid  = threadIdx.x;
    const int wid  = tid >> 5;
    const int lane = tid & 31;

    // ---- one-time per block: shared MLP weights into smem ----
    for (int i = tid; i < 1552; i += 256)   // state_w1 64x97 natural (odd stride)
        ((float4*)(smf + OFF_SW1))[i] = ((const float4*)sw1g)[i];
    for (int i = tid; i < 2048; i += 256) { // state_w2 [d][h] pad 65
        int d = i >> 6, h2 = i & 63;
        smf[OFF_SW2 + d*65 + h2] = sw2g[i];
    }
    for (int i = tid; i < 6144; i += 256) { // msg_w1 [h][i] pad 97
        int hh = i / 96, ii = i - hh*96;
        smf[OFF_MW1 + hh*97 + ii] = mw1g[i];
    }
    for (int i = tid; i < 2048; i += 256) { // msg_w2 [d][h] pad 65
        int d = i >> 6, h2 = i & 63;
        smf[OFF_MW2 + d*65 + h2] = mw2g[i];
    }
    if (tid < 64) smf[OFF_SB1 + tid] = sb1g[tid];
    if (tid < 32) smf[OFF_SB2 + tid] = sb2g[tid];
    if (tid < 64) smf[OFF_MB1 + tid] = mb1g[tid];
    if (tid < 32) smf[OFF_MB2 + tid] = mb2g[tid];
    __syncthreads();

    for (int n = blockIdx.x; n < NNN; n += GRID_A) {
        const int nc = n >> 8;
        const int c  = n & 255;
        const bool isb = (c >= 4 && c < 20);

        // ---- phase 0: per-neuron loads ----
        {
            const float4* w1src = (const float4*)(modw1 + (size_t)n * (32*MODIN));
            for (int i = tid; i < 904; i += 256) ((float4*)(smf + OFF_W1S))[i] = w1src[i];
            const float4* w2src = (const float4*)(modw2 + (size_t)n * (32*MODOUT));
            for (int i = tid; i < 456; i += 256) ((float4*)(smf + OFF_W2S))[i] = w2src[i];
            if (tid < 32) smf[OFF_MB1S + tid] = modb1g[n*32 + tid];
            if (tid < 57) smf[OFF_MB2S + tid] = modb2g[n*57 + tid];
            if (tid < 16) ((int*)(smf + OFF_CIDX))[tid] = conn[n*16 + tid];
            if (isb && tid < 8)
                ((int*)(smf + OFF_BIDX))[tid] = bconn[(nc*16 + (c-4))*8 + tid];

            // batch-major inputs: warp = batch, lane = d
            size_t nb = (size_t)wid * NNN + n;
            float hv = hin[nb*32 + lane];
            smf[OFF_XIN + (16+lane)*8 + wid] = hv;
            smf[OFF_SINT + lane*8 + wid] = hv;
            float pv = prim[nb*32 + lane];
            smf[OFF_XIN + (49+lane)*8 + wid] = pv;
            float nv = nidg[(size_t)n*32 + lane];
            smf[OFF_XIN + (81+lane)*8 + wid] = nv;
            smf[OFF_MINT + (64+lane)*8 + wid] = nv;
            if (lane < 16) smf[OFF_XIN + lane*8 + wid] = trc[nb*16 + lane];
            if (lane == 0) smf[OFF_XIN + 48*8 + wid] = dlog[nb];
        }
        __syncthreads();

        // ---- phase 1: mod layer1 O=32 K=113, K-split over 8 warps ----
        {
            int kb = (113*wid) >> 3, ke = (113*(wid+1)) >> 3;
            gemv_part(smf + OFF_W1S + lane*MODIN, 1, smf + OFF_XIN,
                      smf + OFF_PSUM + (wid*32 + lane)*8, kb, ke);
        }
        __syncthreads();
        {
            float s = smf[OFF_MB1S + (tid >> 3)];
#pragma unroll
            for (int w = 0; w < 8; w++) s += smf[OFF_PSUM + w*256 + tid];
            smf[OFF_HID + tid] = mytanh(s);
        }
        __syncthreads();

        // ---- phase 2: mod layer2 O=57 K=32 ----
        {
            int half = wid >> 2;                 // 0: outputs 0..31, 1: 32..56
            int kb = (wid & 3) * 8, ke = kb + 8;
            int o = half*32 + lane;
            if (half == 0 || lane < 25)
                gemv_part(smf + OFF_W2S + o, MODOUT, smf + OFF_HID,
                          smf + OFF_PSUM + (wid*32 + lane)*8, kb, ke);
        }
        __syncthreads();
        {
            for (int v = tid; v < 456; v += 256) {
                int o = v >> 3;
                float s = smf[OFF_MB2S + o];
                if (o < 32) {
#pragma unroll
                    for (int w = 0; w < 4; w++) s += smf[OFF_PSUM + w*256 + v];
                } else {
#pragma unroll
                    for (int w = 4; w < 8; w++) s += smf[OFF_PSUM + w*256 + (v-256)];
                }
                smf[OFF_OUTS + v] = s;
            }
        }
        __syncthreads();

        // ---- phase 3a: sigmoids (conn 0..15, border 16..23, decay 24) ----
        if (tid < 200) smf[OFF_ACT + tid] = sigm(smf[OFF_OUTS + tid]);
        __syncthreads();

        // ---- phase 3b: received + prim_new + decay into SINT/MINT ----
        {
            size_t bb = (size_t)wid * NNN;
            float acc = 0.0f;
#pragma unroll
            for (int k = 0; k < 16; k++) {
                int ci = ((const int*)(smf + OFF_CIDX))[k];
                acc = fmaf(pm[(bb + nc*256 + ci)*32 + lane],
                           smf[OFF_ACT + k*8 + wid], acc);
            }
            if (isb) {
#pragma unroll
                for (int kb2 = 0; kb2 < 8; kb2++) {
                    int bi = ((const int*)(smf + OFF_BIDX))[kb2];
                    acc = fmaf(pm[(bb + (bi>>4)*256 + 4 + (bi&15))*32 + lane],
                               smf[OFF_ACT + 128 + kb2*8 + wid], acc);
                }
            }
            if (c < 4) acc += ccs[wid*2048 + nc*32 + lane];
            smf[OFF_SINT + (32+lane)*8 + wid] = acc;
            smf[OFF_MINT + (32+lane)*8 + wid] = acc;
            float pnew = smf[OFF_XIN + (49+lane)*8 + wid] + smf[OFF_OUTS + (25+lane)*8 + wid];
            smf[OFF_SINT + (64+lane)*8 + wid] = pnew;
            if (lane == 0) smf[OFF_SINT + 96*8 + wid] = smf[OFF_ACT + 192 + wid];
        }
        __syncthreads();

        // ---- phase 4: state layer1 O=64 K=97 ----
        {
            int tile = wid & 1, s4 = wid >> 1;
            int kb = (97*s4) >> 2, ke = (97*(s4+1)) >> 2;
            int o = tile*32 + lane;
            gemv_part(smf + OFF_SW1 + o*97, 1, smf + OFF_SINT,
                      smf + OFF_PSUM + (wid*32 + lane)*8, kb, ke);
        }
        __syncthreads();
        {
            for (int v = tid; v < 512; v += 256) {
                int tile = v >> 8, r = v & 255;
                float s = smf[OFF_SB1 + (v >> 3)];
#pragma unroll
                for (int s4 = 0; s4 < 4; s4++) s += smf[OFF_PSUM + (2*s4 + tile)*256 + r];
                smf[OFF_SHST + v] = mytanh(s);
            }
        }
        __syncthreads();

        // ---- phase 5: state layer2 O=32 K=64, h_new ----
        {
            gemv_part(smf + OFF_SW2 + lane*65, 1, smf + OFF_SHST,
                      smf + OFF_PSUM + (wid*32 + lane)*8, wid*8, wid*8 + 8);
        }
        __syncthreads();
        {
            float s = smf[OFF_SB2 + (tid >> 3)];
#pragma unroll
            for (int w = 0; w < 8; w++) s += smf[OFF_PSUM + w*256 + tid];
            int b = tid & 7;
            float dec = smf[OFF_ACT + 192 + b];
            float hv  = smf[OFF_SINT + tid];
            smf[OFF_MINT + tid] = dec*hv + (1.0f - dec)*mytanh(s);
        }
        __syncthreads();

        // ---- phase 6: msg layer1 O=64 K=96 ----
        {
            int tile = wid & 1, s4 = wid >> 1;
            int kb = s4*24, ke = kb + 24;
            int o = tile*32 + lane;
            gemv_part(smf + OFF_MW1 + o*97, 1, smf + OFF_MINT,
                      smf + OFF_PSUM + (wid*32 + lane)*8, kb, ke);
        }
        __syncthreads();
        {
            for (int v = tid; v < 512; v += 256) {
                int tile = v >> 8, r = v & 255;
                float s = smf[OFF_MB1 + (v >> 3)];
#pragma unroll
                for (int s4 = 0; s4 < 4; s4++) s += smf[OFF_PSUM + (2*s4 + tile)*256 + r];
                smf[OFF_SHST + v] = mytanh(s);
            }
        }
        __syncthreads();

        // ---- phase 7: msg layer2 O=32 K=64 ----
        {
            gemv_part(smf + OFF_MW2 + lane*65, 1, smf + OFF_SHST,
                      smf + OFF_PSUM + (wid*32 + lane)*8, wid*8, wid*8 + 8);
        }
        __syncthreads();
        {
            float s = smf[OFF_MB2 + (tid >> 3)];
#pragma unroll
            for (int w = 0; w < 8; w++) s += smf[OFF_PSUM + w*256 + tid];
            smf[OFF_HID + tid] = mytanh(s);   // msg staging
        }
        __syncthreads();

        // ---- phase 8: writeback (warp=b, lane=d, coalesced) ----
        {
            size_t nb = (size_t)wid * NNN + n;
            outp[OUT_H   + nb*32 + lane] = smf[OFF_MINT + lane*8 + wid];
            outp[OUT_MSG + nb*32 + lane] = smf[OFF_HID  + lane*8 + wid];
        }
        __syncthreads();
    }
}

// ---------------- kernel B: hebbian + readout ----------------
#define SMEMB_BYTES (8448*4 + 4096*4)

__global__ void __launch_bounds__(256, 2)
cellB_kernel(const int* __restrict__ conn,
             const float* __restrict__ trc,
             float* __restrict__ outp)
{
    extern __shared__ float smb[];
    float* ms = smb;                    // 256 x 33
    int*   cs = (int*)(smb + 8448);     // 4096
    const int b  = blockIdx.x >> 6;
    const int nc = blockIdx.x & 63;
    const int tid = threadIdx.x;

    const float* msgg = outp + OUT_MSG + ((size_t)b*NNN + nc*256) * 32;
    for (int i = tid; i < 8192; i += 256)
        ms[(i >> 5)*33 + (i & 31)] = msgg[i];
    const int4* cg = (const int4*)(conn + nc*4096);
    for (int i = tid; i < 1024; i += 256) ((int4*)cs)[i] = cg[i];
    __syncthreads();

    const int c = tid;
    float me[32];
#pragma unroll
    for (int d = 0; d < 32; d++) me[d] = ms[c*33 + d];

    const size_t base = (size_t)b*NNN + nc*256 + c;
    float4 t4[4];
#pragma unroll
    for (int j = 0; j < 4; j++) t4[j] = ((const float4*)(trc + base*16))[j];

    float heb[16];
#pragma unroll
    for (int k = 0; k < 16; k++) {
        int ci = cs[c*16 + k];
        const float* nb = &ms[ci*33];
        float a0 = 0.0f, a1 = 0.0f;
#pragma unroll
        for (int d = 0; d < 32; d += 2) {
            a0 = fmaf(me[d],   nb[d],   a0);
            a1 = fmaf(me[d+1], nb[d+1], a1);
        }
        heb[k] = (a0 + a1) * 0.003125f;   // 0.1/32 * dot
    }
    float4* h4 = (float4*)(outp + OUT_HEB + base*16);
    h4[0] = make_float4(fmaf(0.9f,t4[0].x,heb[0]),  fmaf(0.9f,t4[0].y,heb[1]),
                        fmaf(0.9f,t4[0].z,heb[2]),  fmaf(0.9f,t4[0].w,heb[3]));
    h4[1] = make_float4(fmaf(0.9f,t4[1].x,heb[4]),  fmaf(0.9f,t4[1].y,heb[5]),
                        fmaf(0.9f,t4[1].z,heb[6]),  fmaf(0.9f,t4[1].w,heb[7]));
    h4[2] = make_float4(fmaf(0.9f,t4[2].x,heb[8]),  fmaf(0.9f,t4[2].y,heb[9]),
                        fmaf(0.9f,t4[2].z,heb[10]), fmaf(0.9f,t4[2].w,heb[11]));
    h4[3] = make_float4(fmaf(0.9f,t4[3].x,heb[12]), fmaf(0.9f,t4[3].y,heb[13]),
                        fmaf(0.9f,t4[3].z,heb[14]), fmaf(0.9f,t4[3].w,heb[15]));

    if (tid < 32) {
        float r = 0.25f * (ms[252*33 + tid] + ms[253*33 + tid] +
                           ms[254*33 + tid] + ms[255*33 + tid]);
        outp[b*2048 + nc*32 + tid] = r;
    }
}

extern "C" void kernel_launch(void* const* d_in, const int* in_sizes, int n_in,
                              void* d_out, int out_size)
{
    const float* ccs   = (const float*)d_in[0];
    const float* hin   = (const float*)d_in[1];
    const float* pm    = (const float*)d_in[2];
    const float* dlog  = (const float*)d_in[3];
    const float* prim  = (const float*)d_in[4];
    const float* trc   = (const float*)d_in[5];
    const float* sw1   = (const float*)d_in[6];
    const float* sb1   = (const float*)d_in[7];
    const float* sw2   = (const float*)d_in[8];
    const float* sb2   = (const float*)d_in[9];
    const float* mw1   = (const float*)d_in[10];
    const float* mb1   = (const float*)d_in[11];
    const float* mw2   = (const float*)d_in[12];
    const float* mb2   = (const float*)d_in[13];
    const float* modw1 = (const float*)d_in[14];
    const float* modb1 = (const float*)d_in[15];
    const float* modw2 = (const float*)d_in[16];
    const float* modb2 = (const float*)d_in[17];
    const float* nid   = (const float*)d_in[18];
    const int*   conn  = (const int*)d_in[19];
    const int*   bconn = (const int*)d_in[20];
    float* outp = (float*)d_out;

    cudaFuncSetAttribute(cellA_kernel, cudaFuncAttributeMaxDynamicSharedMemorySize, SMEM_BYTES);
    cudaFuncSetAttribute(cellB_kernel, cudaFuncAttributeMaxDynamicSharedMemorySize, SMEMB_BYTES);

    cellA_kernel<<<GRID_A, 256, SMEM_BYTES>>>(
        ccs, hin, pm, dlog, prim, trc,
        sw1, sb1, sw2, sb2, mw1, mb1, mw2, mb2,
        modw1, modb1, modw2, modb2, nid, conn, bconn, outp);

    cellB_kernel<<<512, 256, SMEMB_BYTES>>>(conn, trc, outp);
}

// round 5
// speedup vs baseline: 1.2190x; 1.2190x over previous
#include <cuda_runtime.h>
#include <cuda_bf16.h>

#define NNN     16384
#define MODIN   113
#define MODOUT  57

typedef unsigned long long u64;

#define OUT_H    16384
#define OUT_MSG  (OUT_H + 4194304)
#define OUT_HEB  (OUT_MSG + 4194304)

// per (b,n) scratch row of 64: [0:25) sigmoids (16 conn, 8 border, decay), [25:57) prim_new
__device__ float g_scr[(size_t)8 * NNN * 64];

__device__ __forceinline__ u64 pk2(float w) {
    u64 r; asm("mov.b64 %0, {%1, %1};" : "=l"(r) : "f"(w)); return r;
}
__device__ __forceinline__ void fma2(u64 &a, u64 b, u64 c) {
    asm("fma.rn.f32x2 %0, %1, %2, %0;" : "+l"(a) : "l"(b), "l"(c));
}
__device__ __forceinline__ float mytanh(float x) {
    float e = __expf(2.0f * x);
    return 1.0f - __fdividef(2.0f, e + 1.0f);
}
__device__ __forceinline__ float sigm(float x) {
    return __fdividef(1.0f, 1.0f + __expf(-x));
}

// lane owns one output row; accumulate 8 packed batches for i in [kbeg,kend)
__device__ __forceinline__ void gemv_part(const float* __restrict__ W, int iStride,
                                          const float* __restrict__ X,
                                          float* __restrict__ ps,
                                          int kbeg, int kend)
{
    u64 a0 = 0, a1 = 0, a2 = 0, a3 = 0;
    const float* w = W + kbeg * iStride;
    const u64* x = (const u64*)(X + kbeg * 8);
#pragma unroll 4
    for (int i = kbeg; i < kend; ++i) {
        u64 wp = pk2(*w); w += iStride;
        fma2(a0, wp, x[0]); fma2(a1, wp, x[1]);
        fma2(a2, wp, x[2]); fma2(a3, wp, x[3]);
        x += 4;
    }
    u64* pp = (u64*)ps;
    pp[0] = a0; pp[1] = a1; pp[2] = a2; pp[3] = a3;
}

// =================== K1: per-neuron modulator MLP ===================
#define K1_SW1 0        // 32 x 113
#define K1_SW2 3616     // 32 x 57 ([h][o])
#define K1_SXI 5440     // 113 x 8 batch-major
#define K1_SHD 6344     // 32 x 8
#define K1_SPS 6600     // 4 x 32 x 8
#define K1_TOT 7624

__global__ void __launch_bounds__(128)
modk(const float* __restrict__ hin,  const float* __restrict__ dlog,
     const float* __restrict__ prim, const float* __restrict__ trc,
     const float* __restrict__ modw1, const float* __restrict__ modb1g,
     const float* __restrict__ modw2, const float* __restrict__ modb2g,
     const float* __restrict__ nidg)
{
    __shared__ float s[K1_TOT];
    const int tid = threadIdx.x, wid = tid >> 5, lane = tid & 31;
    const int n = blockIdx.x;

    const float4* w1src = (const float4*)(modw1 + (size_t)n * (32*MODIN));
    for (int i = tid; i < 904; i += 128) ((float4*)(s + K1_SW1))[i] = w1src[i];
    const float4* w2src = (const float4*)(modw2 + (size_t)n * (32*MODOUT));
    for (int i = tid; i < 456; i += 128) ((float4*)(s + K1_SW2))[i] = w2src[i];

#pragma unroll
    for (int bb = 0; bb < 2; bb++) {
        int b = wid + bb*4;
        size_t nb = (size_t)b * NNN + n;
        s[K1_SXI + (16+lane)*8 + b] = hin[nb*32 + lane];
        s[K1_SXI + (49+lane)*8 + b] = prim[nb*32 + lane];
        s[K1_SXI + (81+lane)*8 + b] = nidg[(size_t)n*32 + lane];
        if (lane < 16) s[K1_SXI + lane*8 + b] = trc[nb*16 + lane];
        if (lane == 0) s[K1_SXI + 48*8 + b] = dlog[nb];
    }
    __syncthreads();

    // layer1: O=32, K=113, K-split 4 warps
    {
        int kb = (113*wid) >> 2, ke = (113*(wid+1)) >> 2;
        gemv_part(s + K1_SW1 + lane*MODIN, 1, s + K1_SXI,
                  s + K1_SPS + (wid*32 + lane)*8, kb, ke);
    }
    __syncthreads();
    for (int v = tid; v < 256; v += 128) {
        int o = v >> 3;
        float t = modb1g[n*32 + o];
#pragma unroll
        for (int w = 0; w < 4; w++) t += s[K1_SPS + w*256 + v];
        s[K1_SHD + v] = mytanh(t);
    }
    __syncthreads();

    // layer2: O=57, K=32; warps 0-1 -> o 0..31 (ksplit 2), warps 2-3 -> o 32..56
    {
        int half = wid >> 1, ks = wid & 1;
        int o = half*32 + lane;
        if (half == 0 || lane < 25)
            gemv_part(s + K1_SW2 + o, MODOUT, s + K1_SHD,
                      s + K1_SPS + (wid*32 + lane)*8, ks*16, ks*16 + 16);
    }
    __syncthreads();

    for (int v = tid; v < 512; v += 128) {
        int b = v >> 6, o = v & 63;
        if (o < 57) {
            float t = modb2g[n*57 + o];
            if (o < 32) t += s[K1_SPS + o*8 + b] + s[K1_SPS + 256 + o*8 + b];
            else        t += s[K1_SPS + 512 + (o-32)*8 + b] + s[K1_SPS + 768 + (o-32)*8 + b];
            float val = (o < 25) ? sigm(t) : (t + s[K1_SXI + (49 + (o-25))*8 + b]);
            g_scr[((size_t)b*NNN + n)*64 + o] = val;
        }
    }
}

// =================== K2: gather + state MLP + msg MLP ===================
#define OFF_SW1   0        // 64 x 97
#define OFF_SW2   6208     // 32 x 65 pad
#define OFF_MW1   8288     // 64 x 97 (96 used)
#define OFF_MW2   14496    // 32 x 65 pad
#define OFF_SB1   16576
#define OFF_SB2   16640
#define OFF_MB1   16672
#define OFF_MB2   16736
#define WS_BASE   16768
#define W_SINT 0       // 97 x 8 : h | recv | prim_new | decay
#define W_MINT 776     // 96 x 8 : h_new | recv | nid
#define W_SHST 1544    // 64 x 8
#define W_PSUM 2056    // 4 x 32 x 8
#define W_SIGS 3080    // 25 x 8
#define W_ICON 3280    // 16 ints
#define W_IBRD 3296    // 8 ints
#define WSN    3304
#define K2_FLOATS (WS_BASE + 2*WSN)
#define K2_BYTES  (K2_FLOATS*4)
#define GRID_K2 296
#define K2_ITERS ((NNN + GRID_K2*2 - 1) / (GRID_K2*2))

__global__ void __launch_bounds__(256, 2)
cellK2(const float* __restrict__ ccs, const float* __restrict__ hin,
       const float* __restrict__ pm,
       const float* __restrict__ sw1g, const float* __restrict__ sb1g,
       const float* __restrict__ sw2g, const float* __restrict__ sb2g,
       const float* __restrict__ mw1g, const float* __restrict__ mb1g,
       const float* __restrict__ mw2g, const float* __restrict__ mb2g,
       const float* __restrict__ nidg,
       const int*   __restrict__ conn, const int* __restrict__ bconn,
       float* __restrict__ outp)
{
    extern __shared__ float smf[];
    const int tid  = threadIdx.x;
    const int lane = tid & 31;
    const int grp  = tid >> 7;          // neuron slot 0/1
    const int gtid = tid & 127;
    const int gw   = (tid >> 5) & 3;    // warp within group

    for (int i = tid; i < 1552; i += 256)
        ((float4*)(smf + OFF_SW1))[i] = ((const float4*)sw1g)[i];
    for (int i = tid; i < 2048; i += 256) {
        int d = i >> 6, h2 = i & 63;
        smf[OFF_SW2 + d*65 + h2] = sw2g[i];
        smf[OFF_MW2 + d*65 + h2] = mw2g[i];
    }
    for (int i = tid; i < 6144; i += 256) {
        int hh = i / 96, ii = i - hh*96;
        smf[OFF_MW1 + hh*97 + ii] = mw1g[i];
    }
    if (tid < 64) smf[OFF_SB1 + tid] = sb1g[tid];
    if (tid < 32) smf[OFF_SB2 + tid] = sb2g[tid];
    if (tid < 64) smf[OFF_MB1 + tid] = mb1g[tid];
    if (tid < 32) smf[OFF_MB2 + tid] = mb2g[tid];
    __syncthreads();

    float* ws  = smf + WS_BASE + grp*WSN;
    int*   wsi = (int*)ws;

    for (int it = 0; it < K2_ITERS; it++) {
        const int nj = it*(GRID_K2*2) + blockIdx.x*2 + grp;
        const bool act = (nj < NNN);
        const int nc = nj >> 8, c = nj & 255;
        const bool isb = (c >= 4 && c < 20);

        // ---- P0: loads ----
        if (act) {
            if (gw == 0 && lane < 16) wsi[W_ICON + lane] = conn[nj*16 + lane];
            if (gw == 1 && isb && lane < 8)
                wsi[W_IBRD + lane] = bconn[(nc*16 + (c-4))*8 + lane];
#pragma unroll
            for (int bb = 0; bb < 2; bb++) {
                int b = gw*2 + bb;
                size_t nb = (size_t)b * NNN + nj;
                const float* sc = g_scr + nb*64;
                ws[W_SINT + lane*8 + b]      = hin[nb*32 + lane];
                ws[W_SINT + (64+lane)*8 + b] = sc[25 + lane];
                ws[W_MINT + (64+lane)*8 + b] = nidg[(size_t)nj*32 + lane];
                if (lane < 25) {
                    float sv = sc[lane];
                    ws[W_SIGS + lane*8 + b] = sv;
                    if (lane == 24) ws[W_SINT + 96*8 + b] = sv;
                }
            }
        }
        __syncthreads();

        // ---- P1: gather ----
        if (act) {
#pragma unroll
            for (int bb = 0; bb < 2; bb++) {
                int b = gw*2 + bb;
                size_t bbase = (size_t)b * NNN;
                float acc = (c < 4) ? ccs[b*2048 + nc*32 + lane] : 0.0f;
#pragma unroll
                for (int k = 0; k < 16; k++) {
                    int ci = wsi[W_ICON + k];
                    acc = fmaf(pm[(bbase + nc*256 + ci)*32 + lane],
                               ws[W_SIGS + k*8 + b], acc);
                }
                if (isb) {
#pragma unroll
                    for (int k2 = 0; k2 < 8; k2++) {
                        int bi = wsi[W_IBRD + k2];
                        acc = fmaf(pm[(bbase + (bi>>4)*256 + 4 + (bi&15))*32 + lane],
                                   ws[W_SIGS + (16+k2)*8 + b], acc);
                    }
                }
                ws[W_SINT + (32+lane)*8 + b] = acc;
                ws[W_MINT + (32+lane)*8 + b] = acc;
            }
        }
        __syncthreads();

        // ---- P2: state l1 O=64 K=97 (tile x ksplit2) ----
        {
            int tile = gw & 1, s2 = gw >> 1;
            int kb = (97*s2) >> 1, ke = (97*(s2+1)) >> 1;
            gemv_part(smf + OFF_SW1 + (tile*32 + lane)*97, 1, ws + W_SINT,
                      ws + W_PSUM + (gw*32 + lane)*8, kb, ke);
        }
        __syncthreads();
        for (int v = gtid; v < 512; v += 128) {
            int t = v >> 8, r = v & 255;
            float sv = smf[OFF_SB1 + (v >> 3)]
                     + ws[W_PSUM + t*256 + r] + ws[W_PSUM + (t+2)*256 + r];
            ws[W_SHST + v] = mytanh(sv);
        }
        __syncthreads();

        // ---- P3: state l2 O=32 K=64 (ksplit4), h_new ----
        gemv_part(smf + OFF_SW2 + lane*65, 1, ws + W_SHST,
                  ws + W_PSUM + (gw*32 + lane)*8, gw*16, gw*16 + 16);
        __syncthreads();
        for (int v = gtid; v < 256; v += 128) {
            float sv = smf[OFF_SB2 + (v >> 3)];
#pragma unroll
            for (int w = 0; w < 4; w++) sv += ws[W_PSUM + w*256 + v];
            int b = v & 7;
            float dec = ws[W_SINT + 96*8 + b];
            float hv  = ws[W_SINT + v];
            ws[W_MINT + v] = dec*hv + (1.0f - dec)*mytanh(sv);
        }
        __syncthreads();

        // ---- P4: msg l1 O=64 K=96 ----
        {
            int tile = gw & 1, s2 = gw >> 1;
            gemv_part(smf + OFF_MW1 + (tile*32 + lane)*97, 1, ws + W_MINT,
                      ws + W_PSUM + (gw*32 + lane)*8, s2*48, s2*48 + 48);
        }
        __syncthreads();
        for (int v = gtid; v < 512; v += 128) {
            int t = v >> 8, r = v & 255;
            float sv = smf[OFF_MB1 + (v >> 3)]
                     + ws[W_PSUM + t*256 + r] + ws[W_PSUM + (t+2)*256 + r];
            ws[W_SHST + v] = mytanh(sv);
        }
        __syncthreads();

        // ---- P5: msg l2 O=32 K=64 ----
        gemv_part(smf + OFF_MW2 + lane*65, 1, ws + W_SHST,
                  ws + W_PSUM + (gw*32 + lane)*8, gw*16, gw*16 + 16);
        __syncthreads();
        for (int v = gtid; v < 256; v += 128) {
            float sv = smf[OFF_MB2 + (v >> 3)];
#pragma unroll
            for (int w = 0; w < 4; w++) sv += ws[W_PSUM + w*256 + v];
            ws[W_SINT + v] = mytanh(sv);    // msg (h slot now free)
        }
        __syncthreads();

        // ---- P6: writeback ----
        if (act) {
#pragma unroll
            for (int bb = 0; bb < 2; bb++) {
                int b = gw*2 + bb;
                size_t nb = (size_t)b * NNN + nj;
                outp[OUT_H   + nb*32 + lane] = ws[W_MINT + lane*8 + b];
                outp[OUT_MSG + nb*32 + lane] = ws[W_SINT + lane*8 + b];
            }
        }
        __syncthreads();
    }
}

// ---------------- kernel B: hebbian + readout ----------------
#define SMEMB_BYTES (8448*4 + 4096*4)

__global__ void __launch_bounds__(256, 2)
cellB_kernel(const int* __restrict__ conn,
             const float* __restrict__ trc,
             float* __restrict__ outp)
{
    extern __shared__ float smb[];
    float* ms = smb;                    // 256 x 33
    int*   cs = (int*)(smb + 8448);     // 4096
    const int b  = blockIdx.x >> 6;
    const int nc = blockIdx.x & 63;
    const int tid = threadIdx.x;

    const float* msgg = outp + OUT_MSG + ((size_t)b*NNN + nc*256) * 32;
    for (int i = tid; i < 8192; i += 256)
        ms[(i >> 5)*33 + (i & 31)] = msgg[i];
    const int4* cg = (const int4*)(conn + nc*4096);
    for (int i = tid; i < 1024; i += 256) ((int4*)cs)[i] = cg[i];
    __syncthreads();

    const int c = tid;
    float me[32];
#pragma unroll
    for (int d = 0; d < 32; d++) me[d] = ms[c*33 + d];

    const size_t base = (size_t)b*NNN + nc*256 + c;
    float4 t4[4];
#pragma unroll
    for (int j = 0; j < 4; j++) t4[j] = ((const float4*)(trc + base*16))[j];

    float heb[16];
#pragma unroll
    for (int k = 0; k < 16; k++) {
        int ci = cs[c*16 + k];
        const float* nb = &ms[ci*33];
        float a0 = 0.0f, a1 = 0.0f;
#pragma unroll
        for (int d = 0; d < 32; d += 2) {
            a0 = fmaf(me[d],   nb[d],   a0);
            a1 = fmaf(me[d+1], nb[d+1], a1);
        }
        heb[k] = (a0 + a1) * 0.003125f;
    }
    float4* h4 = (float4*)(outp + OUT_HEB + base*16);
    h4[0] = make_float4(fmaf(0.9f,t4[0].x,heb[0]),  fmaf(0.9f,t4[0].y,heb[1]),
                        fmaf(0.9f,t4[0].z,heb[2]),  fmaf(0.9f,t4[0].w,heb[3]));
    h4[1] = make_float4(fmaf(0.9f,t4[1].x,heb[4]),  fmaf(0.9f,t4[1].y,heb[5]),
                        fmaf(0.9f,t4[1].z,heb[6]),  fmaf(0.9f,t4[1].w,heb[7]));
    h4[2] = make_float4(fmaf(0.9f,t4[2].x,heb[8]),  fmaf(0.9f,t4[2].y,heb[9]),
                        fmaf(0.9f,t4[2].z,heb[10]), fmaf(0.9f,t4[2].w,heb[11]));
    h4[3] = make_float4(fmaf(0.9f,t4[3].x,heb[12]), fmaf(0.9f,t4[3].y,heb[13]),
                        fmaf(0.9f,t4[3].z,heb[14]), fmaf(0.9f,t4[3].w,heb[15]));

    if (tid < 32) {
        float r = 0.25f * (ms[252*33 + tid] + ms[253*33 + tid] +
                           ms[254*33 + tid] + ms[255*33 + tid]);
        outp[b*2048 + nc*32 + tid] = r;
    }
}

extern "C" void kernel_launch(void* const* d_in, const int* in_sizes, int n_in,
                              void* d_out, int out_size)
{
    const float* ccs   = (const float*)d_in[0];
    const float* hin   = (const float*)d_in[1];
    const float* pm    = (const float*)d_in[2];
    const float* dlog  = (const float*)d_in[3];
    const float* prim  = (const float*)d_in[4];
    const float* trc   = (const float*)d_in[5];
    const float* sw1   = (const float*)d_in[6];
    const float* sb1   = (const float*)d_in[7];
    const float* sw2   = (const float*)d_in[8];
    const float* sb2   = (const float*)d_in[9];
    const float* mw1   = (const float*)d_in[10];
    const float* mb1   = (const float*)d_in[11];
    const float* mw2   = (const float*)d_in[12];
    const float* mb2   = (const float*)d_in[13];
    const float* modw1 = (const float*)d_in[14];
    const float* modb1 = (const float*)d_in[15];
    const float* modw2 = (const float*)d_in[16];
    const float* modb2 = (const float*)d_in[17];
    const float* nid   = (const float*)d_in[18];
    const int*   conn  = (const int*)d_in[19];
    const int*   bconn = (const int*)d_in[20];
    float* outp = (float*)d_out;

    cudaFuncSetAttribute(cellK2, cudaFuncAttributeMaxDynamicSharedMemorySize, K2_BYTES);
    cudaFuncSetAttribute(cellB_kernel, cudaFuncAttributeMaxDynamicSharedMemorySize, SMEMB_BYTES);

    modk<<<NNN, 128>>>(hin, dlog, prim, trc, modw1, modb1, modw2, modb2, nid);

    cellK2<<<GRID_K2, 256, K2_BYTES>>>(
        ccs, hin, pm, sw1, sb1, sw2, sb2, mw1, mb1, mw2, mb2,
        nid, conn, bconn, outp);

    cellB_kernel<<<512, 256, SMEMB_BYTES>>>(conn, trc, outp);
}

// round 6
// speedup vs baseline: 1.5725x; 1.2900x over previous
#include <cuda_runtime.h>
#include <cuda_bf16.h>

#define NNN     16384
#define MODIN   113
#define MODOUT  57

typedef unsigned long long u64;

#define OUT_H    16384
#define OUT_MSG  (OUT_H + 4194304)
#define OUT_HEB  (OUT_MSG + 4194304)

// per (b,n) scratch row of 64: [0:25) sigmoids (16 conn, 8 border, decay), [25:57) prim_new
__device__ float g_scr[(size_t)8 * NNN * 64];

__device__ __forceinline__ u64 pk2(float w) {
    u64 r; asm("mov.b64 %0, {%1, %1};" : "=l"(r) : "f"(w)); return r;
}
__device__ __forceinline__ void fma2(u64 &a, u64 b, u64 c) {
    asm("fma.rn.f32x2 %0, %1, %2, %0;" : "+l"(a) : "l"(b), "l"(c));
}
__device__ __forceinline__ void upk2(u64 v, float &lo, float &hi) {
    asm("mov.b64 {%0,%1}, %2;" : "=f"(lo), "=f"(hi) : "l"(v));
}
__device__ __forceinline__ float mytanh(float x) {
    float e = __expf(2.0f * x);
    return 1.0f - __fdividef(2.0f, e + 1.0f);
}
__device__ __forceinline__ float sigm(float x) {
    return __fdividef(1.0f, 1.0f + __expf(-x));
}

// psum-writing partial GEMV (used by modk); x loads via LDS.128
__device__ __forceinline__ void gemv_part(const float* __restrict__ W, int iStride,
                                          const float* __restrict__ X,
                                          float* __restrict__ ps,
                                          int kbeg, int kend)
{
    u64 a0 = 0, a1 = 0, a2 = 0, a3 = 0;
    const float* w = W + kbeg * iStride;
    const ulonglong2* x = (const ulonglong2*)(X + kbeg * 8);
#pragma unroll 4
    for (int i = kbeg; i < kend; ++i) {
        u64 wp = pk2(*w); w += iStride;
        ulonglong2 v0 = x[0], v1 = x[1]; x += 2;
        fma2(a0, wp, v0.x); fma2(a1, wp, v0.y);
        fma2(a2, wp, v1.x); fma2(a3, wp, v1.y);
    }
    u64* pp = (u64*)ps;
    pp[0] = a0; pp[1] = a1; pp[2] = a2; pp[3] = a3;
}

// full-K GEMV, lane owns ONE output row (8 packed batches)
__device__ __forceinline__ void gemv1(const float* __restrict__ W,
                                      const float* __restrict__ X,
                                      int K, u64* A)
{
    u64 a0 = 0, a1 = 0, a2 = 0, a3 = 0;
    const ulonglong2* x = (const ulonglong2*)X;
#pragma unroll 4
    for (int i = 0; i < K; ++i) {
        u64 wp = pk2(W[i]);
        ulonglong2 v0 = x[0], v1 = x[1]; x += 2;
        fma2(a0, wp, v0.x); fma2(a1, wp, v0.y);
        fma2(a2, wp, v1.x); fma2(a3, wp, v1.y);
    }
    A[0] = a0; A[1] = a1; A[2] = a2; A[3] = a3;
}

// full-K GEMV, lane owns TWO output rows
__device__ __forceinline__ void gemv2(const float* __restrict__ W0,
                                      const float* __restrict__ W1,
                                      const float* __restrict__ X,
                                      int K, u64* A)
{
    u64 a0=0,a1=0,a2=0,a3=0,a4=0,a5=0,a6=0,a7=0;
    const ulonglong2* x = (const ulonglong2*)X;
#pragma unroll 4
    for (int i = 0; i < K; ++i) {
        u64 p0 = pk2(W0[i]), p1 = pk2(W1[i]);
        ulonglong2 v0 = x[0], v1 = x[1]; x += 2;
        fma2(a0, p0, v0.x); fma2(a1, p0, v0.y);
        fma2(a2, p0, v1.x); fma2(a3, p0, v1.y);
        fma2(a4, p1, v0.x); fma2(a5, p1, v0.y);
        fma2(a6, p1, v1.x); fma2(a7, p1, v1.y);
    }
    A[0]=a0; A[1]=a1; A[2]=a2; A[3]=a3;
    A[4]=a4; A[5]=a5; A[6]=a6; A[7]=a7;
}

// tanh(bias + acc) for 8 packed values -> 2 float4 stores
__device__ __forceinline__ void act_store(float* dst, const u64* A, float bias)
{
    float lo, hi; float4 f0, f1;
    upk2(A[0], lo, hi); f0.x = mytanh(bias + lo); f0.y = mytanh(bias + hi);
    upk2(A[1], lo, hi); f0.z = mytanh(bias + lo); f0.w = mytanh(bias + hi);
    upk2(A[2], lo, hi); f1.x = mytanh(bias + lo); f1.y = mytanh(bias + hi);
    upk2(A[3], lo, hi); f1.z = mytanh(bias + lo); f1.w = mytanh(bias + hi);
    ((float4*)dst)[0] = f0; ((float4*)dst)[1] = f1;
}

// =================== K1: per-neuron modulator MLP ===================
#define K1_SW1 0        // 32 x 113
#define K1_SW2 3616     // 32 x 57 ([h][o])
#define K1_SXI 5440     // 113 x 8 batch-major
#define K1_SHD 6344     // 32 x 8
#define K1_SPS 6600     // 4 x 32 x 8
#define K1_TOT 7624

__global__ void __launch_bounds__(128)
modk(const float* __restrict__ hin,  const float* __restrict__ dlog,
     const float* __restrict__ prim, const float* __restrict__ trc,
     const float* __restrict__ modw1, const float* __restrict__ modb1g,
     const float* __restrict__ modw2, const float* __restrict__ modb2g,
     const float* __restrict__ nidg)
{
    __shared__ float s[K1_TOT];
    const int tid = threadIdx.x, wid = tid >> 5, lane = tid & 31;
    const int n = blockIdx.x;

    const float4* w1src = (const float4*)(modw1 + (size_t)n * (32*MODIN));
    for (int i = tid; i < 904; i += 128) ((float4*)(s + K1_SW1))[i] = w1src[i];
    const float4* w2src = (const float4*)(modw2 + (size_t)n * (32*MODOUT));
    for (int i = tid; i < 456; i += 128) ((float4*)(s + K1_SW2))[i] = w2src[i];

#pragma unroll
    for (int bb = 0; bb < 2; bb++) {
        int b = wid + bb*4;
        size_t nb = (size_t)b * NNN + n;
        s[K1_SXI + (16+lane)*8 + b] = hin[nb*32 + lane];
        s[K1_SXI + (49+lane)*8 + b] = prim[nb*32 + lane];
        s[K1_SXI + (81+lane)*8 + b] = nidg[(size_t)n*32 + lane];
        if (lane < 16) s[K1_SXI + lane*8 + b] = trc[nb*16 + lane];
        if (lane == 0) s[K1_SXI + 48*8 + b] = dlog[nb];
    }
    __syncthreads();

    // layer1: O=32, K=113, K-split 4 warps
    {
        int kb = (113*wid) >> 2, ke = (113*(wid+1)) >> 2;
        gemv_part(s + K1_SW1 + lane*MODIN, 1, s + K1_SXI,
                  s + K1_SPS + (wid*32 + lane)*8, kb, ke);
    }
    __syncthreads();
    for (int v = tid; v < 256; v += 128) {
        int o = v >> 3;
        float t = modb1g[n*32 + o];
#pragma unroll
        for (int w = 0; w < 4; w++) t += s[K1_SPS + w*256 + v];
        s[K1_SHD + v] = mytanh(t);
    }
    __syncthreads();

    // layer2: O=57, K=32
    {
        int half = wid >> 1, ks = wid & 1;
        int o = half*32 + lane;
        if (half == 0 || lane < 25)
            gemv_part(s + K1_SW2 + o, MODOUT, s + K1_SHD,
                      s + K1_SPS + (wid*32 + lane)*8, ks*16, ks*16 + 16);
    }
    __syncthreads();

    for (int v = tid; v < 512; v += 128) {
        int b = v >> 6, o = v & 63;
        if (o < 57) {
            float t = modb2g[n*57 + o];
            if (o < 32) t += s[K1_SPS + o*8 + b] + s[K1_SPS + 256 + o*8 + b];
            else        t += s[K1_SPS + 512 + (o-32)*8 + b] + s[K1_SPS + 768 + (o-32)*8 + b];
            float val = (o < 25) ? sigm(t) : (t + s[K1_SXI + (49 + (o-25))*8 + b]);
            g_scr[((size_t)b*NNN + n)*64 + o] = val;
        }
    }
}

// =================== K2: warp-per-neuron gather + state/msg MLPs ===================
#define OFF_SW1   0        // 64 x 97
#define OFF_SW2   6208     // 32 x 65 pad
#define OFF_MW1   8288     // 64 x 97 (96 used)
#define OFF_MW2   14496    // 32 x 65 pad
#define OFF_SB1   16576
#define OFF_SB2   16640
#define OFF_MB1   16672
#define OFF_MB2   16736
#define WS_BASE   16768
// per-warp workspace (floats): X 97x8 | SG 25x8 | ICON 16i | IBRD 8i | pad | SH 64x8
#define W_SG    776
#define W_ICONI 976     // int index within ws
#define W_IBRDI 992
#define W_SH    1000
#define WSN     1512
#define K2_WARPS 6
#define K2_FLOATS (WS_BASE + K2_WARPS*WSN)
#define K2_BYTES  (K2_FLOATS*4)
#define GRID_K2 296
#define TOT_WARPS (GRID_K2*K2_WARPS)

__global__ void __launch_bounds__(192, 2)
cellK2(const float* __restrict__ ccs, const float* __restrict__ hin,
       const float* __restrict__ pm,
       const float* __restrict__ sw1g, const float* __restrict__ sb1g,
       const float* __restrict__ sw2g, const float* __restrict__ sb2g,
       const float* __restrict__ mw1g, const float* __restrict__ mb1g,
       const float* __restrict__ mw2g, const float* __restrict__ mb2g,
       const float* __restrict__ nidg,
       const int*   __restrict__ conn, const int* __restrict__ bconn,
       float* __restrict__ outp)
{
    extern __shared__ float smf[];
    const int tid  = threadIdx.x;
    const int wid  = tid >> 5;
    const int lane = tid & 31;

    // ---- one-time staging of shared MLP weights ----
    for (int i = tid; i < 1552; i += 192)
        ((float4*)(smf + OFF_SW1))[i] = ((const float4*)sw1g)[i];
    for (int i = tid; i < 2048; i += 192) {
        int d = i >> 6, h2 = i & 63;
        smf[OFF_SW2 + d*65 + h2] = sw2g[i];
        smf[OFF_MW2 + d*65 + h2] = mw2g[i];
    }
    for (int i = tid; i < 6144; i += 192) {
        int hh = i / 96, ii = i - hh*96;
        smf[OFF_MW1 + hh*97 + ii] = mw1g[i];
    }
    if (tid < 64) smf[OFF_SB1 + tid] = sb1g[tid];
    if (tid < 32) smf[OFF_SB2 + tid] = sb2g[tid];
    if (tid < 64) smf[OFF_MB1 + tid] = mb1g[tid];
    if (tid < 32) smf[OFF_MB2 + tid] = mb2g[tid];
    __syncthreads();

    float* ws = smf + WS_BASE + wid*WSN;
    int*   wi = (int*)ws;

    const int gwarp = blockIdx.x*K2_WARPS + wid;

    for (int n = gwarp; n < NNN; n += TOT_WARPS) {
        const int nc = n >> 8, c = n & 255;
        const bool isb = (c >= 4 && c < 20);

        // ---- P0: loads (X rows: 0-31 h, 64-95 prim_new, 96 decay; SG sigmoids)
        if (lane < 16) wi[W_ICONI + lane] = conn[n*16 + lane];
        if (isb && lane < 8) wi[W_IBRDI + lane] = bconn[(nc*16 + (c-4))*8 + lane];
        float nidv = nidg[(size_t)n*32 + lane];
#pragma unroll
        for (int b = 0; b < 8; b++) {
            size_t nb = (size_t)b * NNN + n;
            ws[lane*8 + b]      = hin[nb*32 + lane];
            ws[(64+lane)*8 + b] = g_scr[nb*64 + 25 + lane];
            if (lane < 25) {
                float sv = g_scr[nb*64 + lane];
                ws[W_SG + lane*8 + b] = sv;
                if (lane == 24) ws[96*8 + b] = sv;
            }
        }
        __syncwarp();

        // ---- P1: gather -> X rows 32-63 (recv)
#pragma unroll
        for (int b = 0; b < 8; b++) {
            size_t bb = (size_t)b * NNN;
            float acc = (c < 4) ? ccs[b*2048 + nc*32 + lane] : 0.0f;
#pragma unroll
            for (int k = 0; k < 16; k++) {
                int ci = wi[W_ICONI + k];
                acc = fmaf(pm[(bb + nc*256 + ci)*32 + lane], ws[W_SG + k*8 + b], acc);
            }
            if (isb) {
#pragma unroll
                for (int k = 0; k < 8; k++) {
                    int bi = wi[W_IBRDI + k];
                    acc = fmaf(pm[(bb + (bi>>4)*256 + 4 + (bi&15))*32 + lane],
                               ws[W_SG + (16+k)*8 + b], acc);
                }
            }
            ws[(32+lane)*8 + b] = acc;
        }
        __syncwarp();

        // ---- P2: state l1 O=64 K=97, lane owns rows lane & lane+32
        {
            u64 A[8];
            gemv2(smf + OFF_SW1 + lane*97, smf + OFF_SW1 + (lane+32)*97, ws, 97, A);
            act_store(ws + W_SH + lane*8,      A,     smf[OFF_SB1 + lane]);
            act_store(ws + W_SH + (lane+32)*8, A + 4, smf[OFF_SB1 + lane + 32]);
        }
        __syncwarp();

        // ---- P3: state l2 O=32 K=64, h_new in place; nid into rows 64-95
        {
            u64 B[4];
            gemv1(smf + OFF_SW2 + lane*65, ws + W_SH, 64, B);
            float dh[8];
            upk2(B[0], dh[0], dh[1]); upk2(B[1], dh[2], dh[3]);
            upk2(B[2], dh[4], dh[5]); upk2(B[3], dh[6], dh[7]);
            float sb = smf[OFF_SB2 + lane];
#pragma unroll
            for (int b = 0; b < 8; b++) {
                float dec = ws[96*8 + b];
                float hv  = ws[lane*8 + b];
                float hn  = dec*hv + (1.0f - dec)*mytanh(dh[b] + sb);
                ws[lane*8 + b] = hn;
                outp[OUT_H + ((size_t)b*NNN + n)*32 + lane] = hn;
            }
            float4 nf = make_float4(nidv, nidv, nidv, nidv);
            ((float4*)(ws + (64+lane)*8))[0] = nf;
            ((float4*)(ws + (64+lane)*8))[1] = nf;
        }
        __syncwarp();

        // ---- P4: msg l1 O=64 K=96 (X rows: h_new | recv | nid)
        {
            u64 A[8];
            gemv2(smf + OFF_MW1 + lane*97, smf + OFF_MW1 + (lane+32)*97, ws, 96, A);
            act_store(ws + W_SH + lane*8,      A,     smf[OFF_MB1 + lane]);
            act_store(ws + W_SH + (lane+32)*8, A + 4, smf[OFF_MB1 + lane + 32]);
        }
        __syncwarp();

        // ---- P5: msg l2 O=32 K=64 -> STG msg
        {
            u64 B[4];
            gemv1(smf + OFF_MW2 + lane*65, ws + W_SH, 64, B);
            float dm[8];
            upk2(B[0], dm[0], dm[1]); upk2(B[1], dm[2], dm[3]);
            upk2(B[2], dm[4], dm[5]); upk2(B[3], dm[6], dm[7]);
            float mb = smf[OFF_MB2 + lane];
#pragma unroll
            for (int b = 0; b < 8; b++)
                outp[OUT_MSG + ((size_t)b*NNN + n)*32 + lane] = mytanh(dm[b] + mb);
        }
        __syncwarp();
    }
}

// ---------------- kernel B: hebbian + readout (2 threads per neuron) ----------------
#define SMEMB_BYTES (8448*4 + 4096*4)

__global__ void __launch_bounds__(512, 2)
cellB_kernel(const int* __restrict__ conn,
             const float* __restrict__ trc,
             float* __restrict__ outp)
{
    extern __shared__ float smb[];
    float* ms = smb;                    // 256 x 33
    int*   cs = (int*)(smb + 8448);     // 4096
    const int b  = blockIdx.x >> 6;
    const int nc = blockIdx.x & 63;
    const int tid = threadIdx.x;

    const float* msgg = outp + OUT_MSG + ((size_t)b*NNN + nc*256) * 32;
    for (int i = tid; i < 8192; i += 512)
        ms[(i >> 5)*33 + (i & 31)] = msgg[i];
    const int4* cg = (const int4*)(conn + nc*4096);
    for (int i = tid; i < 1024; i += 512) ((int4*)cs)[i] = cg[i];
    __syncthreads();

    const int c  = tid >> 1;
    const int kh = tid & 1;      // k-half: [kh*8, kh*8+8)
    float me[32];
#pragma unroll
    for (int d = 0; d < 32; d++) me[d] = ms[c*33 + d];

    const size_t base = (size_t)b*NNN + nc*256 + c;
    float4 t4[2];
    t4[0] = ((const float4*)(trc + base*16 + kh*8))[0];
    t4[1] = ((const float4*)(trc + base*16 + kh*8))[1];

    float heb[8];
#pragma unroll
    for (int k = 0; k < 8; k++) {
        int ci = cs[c*16 + kh*8 + k];
        const float* nb = &ms[ci*33];
        float a0 = 0.0f, a1 = 0.0f;
#pragma unroll
        for (int d = 0; d < 32; d += 2) {
            a0 = fmaf(me[d],   nb[d],   a0);
            a1 = fmaf(me[d+1], nb[d+1], a1);
        }
        heb[k] = (a0 + a1) * 0.003125f;
    }
    float4* h4 = (float4*)(outp + OUT_HEB + base*16 + kh*8);
    h4[0] = make_float4(fmaf(0.9f,t4[0].x,heb[0]), fmaf(0.9f,t4[0].y,heb[1]),
                        fmaf(0.9f,t4[0].z,heb[2]), fmaf(0.9f,t4[0].w,heb[3]));
    h4[1] = make_float4(fmaf(0.9f,t4[1].x,heb[4]), fmaf(0.9f,t4[1].y,heb[5]),
                        fmaf(0.9f,t4[1].z,heb[6]), fmaf(0.9f,t4[1].w,heb[7]));

    if (tid < 32) {
        float r = 0.25f * (ms[252*33 + tid] + ms[253*33 + tid] +
                           ms[254*33 + tid] + ms[255*33 + tid]);
        outp[b*2048 + nc*32 + tid] = r;
    }
}

extern "C" void kernel_launch(void* const* d_in, const int* in_sizes, int n_in,
                              void* d_out, int out_size)
{
    const float* ccs   = (const float*)d_in[0];
    const float* hin   = (const float*)d_in[1];
    const float* pm    = (const float*)d_in[2];
    const float* dlog  = (const float*)d_in[3];
    const float* prim  = (const float*)d_in[4];
    const float* trc   = (const float*)d_in[5];
    const float* sw1   = (const float*)d_in[6];
    const float* sb1   = (const float*)d_in[7];
    const float* sw2   = (const float*)d_in[8];
    const float* sb2   = (const float*)d_in[9];
    const float* mw1   = (const float*)d_in[10];
    const float* mb1   = (const float*)d_in[11];
    const float* mw2   = (const float*)d_in[12];
    const float* mb2   = (const float*)d_in[13];
    const float* modw1 = (const float*)d_in[14];
    const float* modb1 = (const float*)d_in[15];
    const float* modw2 = (const float*)d_in[16];
    const float* modb2 = (const float*)d_in[17];
    const float* nid   = (const float*)d_in[18];
    const int*   conn  = (const int*)d_in[19];
    const int*   bconn = (const int*)d_in[20];
    float* outp = (float*)d_out;

    cudaFuncSetAttribute(cellK2, cudaFuncAttributeMaxDynamicSharedMemorySize, K2_BYTES);
    cudaFuncSetAttribute(cellB_kernel, cudaFuncAttributeMaxDynamicSharedMemorySize, SMEMB_BYTES);

    modk<<<NNN, 128>>>(hin, dlog, prim, trc, modw1, modb1, modw2, modb2, nid);

    cellK2<<<GRID_K2, 192, K2_BYTES>>>(
        ccs, hin, pm, sw1, sb1, sw2, sb2, mw1, mb1, mw2, mb2,
        nid, conn, bconn, outp);

    cellB_kernel<<<512, 512, SMEMB_BYTES>>>(conn, trc, outp);
}

// round 7
// speedup vs baseline: 1.8726x; 1.1909x over previous
#include <cuda_runtime.h>
#include <cuda_bf16.h>

#define NNN     16384
#define MODIN   113
#define MODOUT  57

typedef unsigned long long u64;

#define OUT_H    16384
#define OUT_MSG  (OUT_H + 4194304)
#define OUT_HEB  (OUT_MSG + 4194304)

// per (b,n) scratch row of 64: [0:25) sigmoids (16 conn, 8 border, decay), [25:57) prim_new
__device__ float g_scr[(size_t)8 * NNN * 64];

__device__ __forceinline__ u64 pk2(float w) {
    u64 r; asm("mov.b64 %0, {%1, %1};" : "=l"(r) : "f"(w)); return r;
}
__device__ __forceinline__ void fma2(u64 &a, u64 b, u64 c) {
    asm("fma.rn.f32x2 %0, %1, %2, %0;" : "+l"(a) : "l"(b), "l"(c));
}
__device__ __forceinline__ void upk2(u64 v, float &lo, float &hi) {
    asm("mov.b64 {%0,%1}, %2;" : "=f"(lo), "=f"(hi) : "l"(v));
}
__device__ __forceinline__ float mytanh(float x) {
    float e = __expf(2.0f * x);
    return 1.0f - __fdividef(2.0f, e + 1.0f);
}
__device__ __forceinline__ float sigm(float x) {
    return __fdividef(1.0f, 1.0f + __expf(-x));
}
__device__ __forceinline__ unsigned smem_u32(const void* p) {
    return (unsigned)__cvta_generic_to_shared(p);
}
__device__ __forceinline__ void cpasync16(unsigned saddr, const void* g) {
    asm volatile("cp.async.cg.shared.global [%0], [%1], 16;" :: "r"(saddr), "l"(g));
}
__device__ __forceinline__ void cp_commit() {
    asm volatile("cp.async.commit_group;");
}
template<int N> __device__ __forceinline__ void cp_wait() {
    asm volatile("cp.async.wait_group %0;" :: "n"(N));
}

// psum-writing partial GEMV; x loads via LDS.128 (broadcast across warp)
__device__ __forceinline__ void gemv_part(const float* __restrict__ W, int iStride,
                                          const float* __restrict__ X,
                                          float* __restrict__ ps,
                                          int kbeg, int kend)
{
    u64 a0 = 0, a1 = 0, a2 = 0, a3 = 0;
    const float* w = W + kbeg * iStride;
    const ulonglong2* x = (const ulonglong2*)(X + kbeg * 8);
#pragma unroll 4
    for (int i = kbeg; i < kend; ++i) {
        u64 wp = pk2(*w); w += iStride;
        ulonglong2 v0 = x[0], v1 = x[1]; x += 2;
        fma2(a0, wp, v0.x); fma2(a1, wp, v0.y);
        fma2(a2, wp, v1.x); fma2(a3, wp, v1.y);
    }
    u64* pp = (u64*)ps;
    pp[0] = a0; pp[1] = a1; pp[2] = a2; pp[3] = a3;
}

// full-K GEMV, lane owns ONE output row (8 packed batches)
__device__ __forceinline__ void gemv1(const float* __restrict__ W,
                                      const float* __restrict__ X,
                                      int K, u64* A)
{
    u64 a0 = 0, a1 = 0, a2 = 0, a3 = 0;
    const ulonglong2* x = (const ulonglong2*)X;
#pragma unroll 4
    for (int i = 0; i < K; ++i) {
        u64 wp = pk2(W[i]);
        ulonglong2 v0 = x[0], v1 = x[1]; x += 2;
        fma2(a0, wp, v0.x); fma2(a1, wp, v0.y);
        fma2(a2, wp, v1.x); fma2(a3, wp, v1.y);
    }
    A[0] = a0; A[1] = a1; A[2] = a2; A[3] = a3;
}

// full-K GEMV, lane owns TWO output rows
__device__ __forceinline__ void gemv2(const float* __restrict__ W0,
                                      const float* __restrict__ W1,
                                      const float* __restrict__ X,
                                      int K, u64* A)
{
    u64 a0=0,a1=0,a2=0,a3=0,a4=0,a5=0,a6=0,a7=0;
    const ulonglong2* x = (const ulonglong2*)X;
#pragma unroll 4
    for (int i = 0; i < K; ++i) {
        u64 p0 = pk2(W0[i]), p1 = pk2(W1[i]);
        ulonglong2 v0 = x[0], v1 = x[1]; x += 2;
        fma2(a0, p0, v0.x); fma2(a1, p0, v0.y);
        fma2(a2, p0, v1.x); fma2(a3, p0, v1.y);
        fma2(a4, p1, v0.x); fma2(a5, p1, v0.y);
        fma2(a6, p1, v1.x); fma2(a7, p1, v1.y);
    }
    A[0]=a0; A[1]=a1; A[2]=a2; A[3]=a3;
    A[4]=a4; A[5]=a5; A[6]=a6; A[7]=a7;
}

// tanh(bias + acc) for 8 packed values -> 2 float4 stores
__device__ __forceinline__ void act_store(float* dst, const u64* A, float bias)
{
    float lo, hi; float4 f0, f1;
    upk2(A[0], lo, hi); f0.x = mytanh(bias + lo); f0.y = mytanh(bias + hi);
    upk2(A[1], lo, hi); f0.z = mytanh(bias + lo); f0.w = mytanh(bias + hi);
    upk2(A[2], lo, hi); f1.x = mytanh(bias + lo); f1.y = mytanh(bias + hi);
    upk2(A[3], lo, hi); f1.z = mytanh(bias + lo); f1.w = mytanh(bias + hi);
    ((float4*)dst)[0] = f0; ((float4*)dst)[1] = f1;
}

// =================== K1: per-neuron modulator MLP (256 thr, cp.async) ===================
#define K1_W1  0        // 32 x 113 = 3616
#define K1_W2  3616     // 32 x 57 ([h][o]) = 1824
#define K1_X   5440     // 113 x 8 batch-major = 904
#define K1_H   6344     // 32 x 8 = 256
#define K1_PS  6600     // 8 x 32 x 8 = 2048
#define K1_TOT 8648     // 34592 B

__global__ void __launch_bounds__(256, 5)
modk(const float* __restrict__ hin,  const float* __restrict__ dlog,
     const float* __restrict__ prim, const float* __restrict__ trc,
     const float* __restrict__ modw1, const float* __restrict__ modb1g,
     const float* __restrict__ modw2, const float* __restrict__ modb2g,
     const float* __restrict__ nidg)
{
    __shared__ float s[K1_TOT];
    const int tid = threadIdx.x, wid = tid >> 5, lane = tid & 31;
    const int n = blockIdx.x;

    // ---- cp.async weight staging: group0 = W1, group1 = W2 ----
    {
        unsigned sW1 = smem_u32(s + K1_W1);
        const float4* g1 = (const float4*)(modw1 + (size_t)n * (32*MODIN));
        for (int i = tid; i < 904; i += 256)
            cpasync16(sW1 + i*16, g1 + i);
        cp_commit();
        unsigned sW2 = smem_u32(s + K1_W2);
        const float4* g2 = (const float4*)(modw2 + (size_t)n * (32*MODOUT));
        for (int i = tid; i < 456; i += 256)
            cpasync16(sW2 + i*16, g2 + i);
        cp_commit();
    }

    // ---- build X (warp = batch, lane = d) ----
    {
        int b = wid;
        size_t nb = (size_t)b * NNN + n;
        s[K1_X + (16+lane)*8 + b] = hin[nb*32 + lane];
        s[K1_X + (49+lane)*8 + b] = prim[nb*32 + lane];
        s[K1_X + (81+lane)*8 + b] = nidg[(size_t)n*32 + lane];
        if (lane < 16) s[K1_X + lane*8 + b] = trc[nb*16 + lane];
        if (lane == 0) s[K1_X + 48*8 + b] = dlog[nb];
    }
    cp_wait<1>();          // W1 landed (W2 may still be in flight)
    __syncthreads();

    // ---- layer1: O=32 (lane), K=113 split over 8 warps ----
    {
        int kb = (113*wid) >> 3, ke = (113*(wid+1)) >> 3;
        gemv_part(s + K1_W1 + lane*MODIN, 1, s + K1_X,
                  s + K1_PS + (wid*32 + lane)*8, kb, ke);
    }
    __syncthreads();
    {
        int o = tid >> 3;
        float t = modb1g[n*32 + o];
#pragma unroll
        for (int w = 0; w < 8; w++) t += s[K1_PS + w*256 + tid];
        s[K1_H + tid] = mytanh(t);
    }
    cp_wait<0>();          // W2 landed
    __syncthreads();

    // ---- layer2: O=57, K=32; warp = (oh = wid&1, kseg = wid>>1) ----
    {
        int oh = wid & 1, kseg = wid >> 1;
        int o = oh*32 + lane;
        if (oh == 0 || lane < 25)
            gemv_part(s + K1_W2 + o, MODOUT, s + K1_H,
                      s + K1_PS + (wid*32 + lane)*8, kseg*8, kseg*8 + 8);
    }
    __syncthreads();

    // ---- reduce + postprocess + write scratch ----
    for (int v = tid; v < 456; v += 256) {
        int o = v >> 3, b = v & 7;
        int oh = o >> 5, ol = o & 31;
        float t = modb2g[n*57 + o];
#pragma unroll
        for (int ks = 0; ks < 4; ks++)
            t += s[K1_PS + (oh + 2*ks)*256 + ol*8 + b];
        float val = (o < 25) ? sigm(t) : (t + s[K1_X + (49 + (o-25))*8 + b]);
        g_scr[((size_t)b*NNN + n)*64 + o] = val;
    }
}

// =================== K2: warp-per-neuron gather + state/msg MLPs ===================
#define OFF_SW1   0        // 64 x 97
#define OFF_SW2   6208     // 32 x 65 pad
#define OFF_MW1   8288     // 64 x 97 (96 used)
#define OFF_MW2   14496    // 32 x 65 pad
#define OFF_SB1   16576
#define OFF_SB2   16640
#define OFF_MB1   16672
#define OFF_MB2   16736
#define WS_BASE   16768
// per-warp workspace (floats): X 97x8 | SG 25x8 | ICON 16i | IBRD 8i | pad | SH 64x8
#define W_SG    776
#define W_ICONI 976     // int index within ws
#define W_IBRDI 992
#define W_SH    1000
#define WSN     1512
#define K2_WARPS 6
#define K2_FLOATS (WS_BASE + K2_WARPS*WSN)
#define K2_BYTES  (K2_FLOATS*4)
#define GRID_K2 296
#define TOT_WARPS (GRID_K2*K2_WARPS)

__global__ void __launch_bounds__(192, 2)
cellK2(const float* __restrict__ ccs, const float* __restrict__ hin,
       const float* __restrict__ pm,
       const float* __restrict__ sw1g, const float* __restrict__ sb1g,
       const float* __restrict__ sw2g, const float* __restrict__ sb2g,
       const float* __restrict__ mw1g, const float* __restrict__ mb1g,
       const float* __restrict__ mw2g, const float* __restrict__ mb2g,
       const float* __restrict__ nidg,
       const int*   __restrict__ conn, const int* __restrict__ bconn,
       float* __restrict__ outp)
{
    extern __shared__ float smf[];
    const int tid  = threadIdx.x;
    const int wid  = tid >> 5;
    const int lane = tid & 31;

    // ---- one-time staging of shared MLP weights ----
    for (int i = tid; i < 1552; i += 192)
        ((float4*)(smf + OFF_SW1))[i] = ((const float4*)sw1g)[i];
    for (int i = tid; i < 2048; i += 192) {
        int d = i >> 6, h2 = i & 63;
        smf[OFF_SW2 + d*65 + h2] = sw2g[i];
        smf[OFF_MW2 + d*65 + h2] = mw2g[i];
    }
    for (int i = tid; i < 6144; i += 192) {
        int hh = i / 96, ii = i - hh*96;
        smf[OFF_MW1 + hh*97 + ii] = mw1g[i];
    }
    if (tid < 64) smf[OFF_SB1 + tid] = sb1g[tid];
    if (tid < 32) smf[OFF_SB2 + tid] = sb2g[tid];
    if (tid < 64) smf[OFF_MB1 + tid] = mb1g[tid];
    if (tid < 32) smf[OFF_MB2 + tid] = mb2g[tid];
    __syncthreads();

    float* ws = smf + WS_BASE + wid*WSN;
    int*   wi = (int*)ws;

    const int gwarp = blockIdx.x*K2_WARPS + wid;

    for (int n = gwarp; n < NNN; n += TOT_WARPS) {
        const int nc = n >> 8, c = n & 255;
        const bool isb = (c >= 4 && c < 20);

        // ---- P0: loads (X rows: 0-31 h, 64-95 prim_new, 96 decay; SG sigmoids)
        if (lane < 16) wi[W_ICONI + lane] = conn[n*16 + lane];
        if (isb && lane < 8) wi[W_IBRDI + lane] = bconn[(nc*16 + (c-4))*8 + lane];
        float nidv = nidg[(size_t)n*32 + lane];
#pragma unroll
        for (int b = 0; b < 8; b++) {
            size_t nb = (size_t)b * NNN + n;
            ws[lane*8 + b]      = hin[nb*32 + lane];
            ws[(64+lane)*8 + b] = g_scr[nb*64 + 25 + lane];
            if (lane < 25) {
                float sv = g_scr[nb*64 + lane];
                ws[W_SG + lane*8 + b] = sv;
                if (lane == 24) ws[96*8 + b] = sv;
            }
        }
        __syncwarp();

        // ---- P1: gather -> X rows 32-63 (recv)
#pragma unroll
        for (int b = 0; b < 8; b++) {
            size_t bb = (size_t)b * NNN;
            float acc = (c < 4) ? ccs[b*2048 + nc*32 + lane] : 0.0f;
#pragma unroll
            for (int k = 0; k < 16; k++) {
                int ci = wi[W_ICONI + k];
                acc = fmaf(pm[(bb + nc*256 + ci)*32 + lane], ws[W_SG + k*8 + b], acc);
            }
            if (isb) {
#pragma unroll
                for (int k = 0; k < 8; k++) {
                    int bi = wi[W_IBRDI + k];
                    acc = fmaf(pm[(bb + (bi>>4)*256 + 4 + (bi&15))*32 + lane],
                               ws[W_SG + (16+k)*8 + b], acc);
                }
            }
            ws[(32+lane)*8 + b] = acc;
        }
        __syncwarp();

        // ---- P2: state l1 O=64 K=97, lane owns rows lane & lane+32
        {
            u64 A[8];
            gemv2(smf + OFF_SW1 + lane*97, smf + OFF_SW1 + (lane+32)*97, ws, 97, A);
            act_store(ws + W_SH + lane*8,      A,     smf[OFF_SB1 + lane]);
            act_store(ws + W_SH + (lane+32)*8, A + 4, smf[OFF_SB1 + lane + 32]);
        }
        __syncwarp();

        // ---- P3: state l2 O=32 K=64, h_new in place; nid into rows 64-95
        {
            u64 B[4];
            gemv1(smf + OFF_SW2 + lane*65, ws + W_SH, 64, B);
            float dh[8];
            upk2(B[0], dh[0], dh[1]); upk2(B[1], dh[2], dh[3]);
            upk2(B[2], dh[4], dh[5]); upk2(B[3], dh[6], dh[7]);
            float sb = smf[OFF_SB2 + lane];
#pragma unroll
            for (int b = 0; b < 8; b++) {
                float dec = ws[96*8 + b];
                float hv  = ws[lane*8 + b];
                float hn  = dec*hv + (1.0f - dec)*mytanh(dh[b] + sb);
                ws[lane*8 + b] = hn;
                outp[OUT_H + ((size_t)b*NNN + n)*32 + lane] = hn;
            }
            float4 nf = make_float4(nidv, nidv, nidv, nidv);
            ((float4*)(ws + (64+lane)*8))[0] = nf;
            ((float4*)(ws + (64+lane)*8))[1] = nf;
        }
        __syncwarp();

        // ---- P4: msg l1 O=64 K=96 (X rows: h_new | recv | nid)
        {
            u64 A[8];
            gemv2(smf + OFF_MW1 + lane*97, smf + OFF_MW1 + (lane+32)*97, ws, 96, A);
            act_store(ws + W_SH + lane*8,      A,     smf[OFF_MB1 + lane]);
            act_store(ws + W_SH + (lane+32)*8, A + 4, smf[OFF_MB1 + lane + 32]);
        }
        __syncwarp();

        // ---- P5: msg l2 O=32 K=64 -> STG msg
        {
            u64 B[4];
            gemv1(smf + OFF_MW2 + lane*65, ws + W_SH, 64, B);
            float dm[8];
            upk2(B[0], dm[0], dm[1]); upk2(B[1], dm[2], dm[3]);
            upk2(B[2], dm[4], dm[5]); upk2(B[3], dm[6], dm[7]);
            float mb = smf[OFF_MB2 + lane];
#pragma unroll
            for (int b = 0; b < 8; b++)
                outp[OUT_MSG + ((size_t)b*NNN + n)*32 + lane] = mytanh(dm[b] + mb);
        }
        __syncwarp();
    }
}

// ---------------- kernel B: hebbian + readout (2 threads per neuron) ----------------
#define SMEMB_BYTES (8448*4 + 4096*4)

__global__ void __launch_bounds__(512, 2)
cellB_kernel(const int* __restrict__ conn,
             const float* __restrict__ trc,
             float* __restrict__ outp)
{
    extern __shared__ float smb[];
    float* ms = smb;                    // 256 x 33
    int*   cs = (int*)(smb + 8448);     // 4096
    const int b  = blockIdx.x >> 6;
    const int nc = blockIdx.x & 63;
    const int tid = threadIdx.x;

    const float* msgg = outp + OUT_MSG + ((size_t)b*NNN + nc*256) * 32;
    for (int i = tid; i < 8192; i += 512)
        ms[(i >> 5)*33 + (i & 31)] = msgg[i];
    const int4* cg = (const int4*)(conn + nc*4096);
    for (int i = tid; i < 1024; i += 512) ((int4*)cs)[i] = cg[i];
    __syncthreads();

    const int c  = tid >> 1;
    const int kh = tid & 1;      // k-half: [kh*8, kh*8+8)
    float me[32];
#pragma unroll
    for (int d = 0; d < 32; d++) me[d] = ms[c*33 + d];

    const size_t base = (size_t)b*NNN + nc*256 + c;
    float4 t4[2];
    t4[0] = ((const float4*)(trc + base*16 + kh*8))[0];
    t4[1] = ((const float4*)(trc + base*16 + kh*8))[1];

    float heb[8];
#pragma unroll
    for (int k = 0; k < 8; k++) {
        int ci = cs[c*16 + kh*8 + k];
        const float* nb = &ms[ci*33];
        float a0 = 0.0f, a1 = 0.0f;
#pragma unroll
        for (int d = 0; d < 32; d += 2) {
            a0 = fmaf(me[d],   nb[d],   a0);
            a1 = fmaf(me[d+1], nb[d+1], a1);
        }
        heb[k] = (a0 + a1) * 0.003125f;
    }
    float4* h4 = (float4*)(outp + OUT_HEB + base*16 + kh*8);
    h4[0] = make_float4(fmaf(0.9f,t4[0].x,heb[0]), fmaf(0.9f,t4[0].y,heb[1]),
                        fmaf(0.9f,t4[0].z,heb[2]), fmaf(0.9f,t4[0].w,heb[3]));
    h4[1] = make_float4(fmaf(0.9f,t4[1].x,heb[4]), fmaf(0.9f,t4[1].y,heb[5]),
                        fmaf(0.9f,t4[1].z,heb[6]), fmaf(0.9f,t4[1].w,heb[7]));

    if (tid < 32) {
        float r = 0.25f * (ms[252*33 + tid] + ms[253*33 + tid] +
                           ms[254*33 + tid] + ms[255*33 + tid]);
        outp[b*2048 + nc*32 + tid] = r;
    }
}

extern "C" void kernel_launch(void* const* d_in, const int* in_sizes, int n_in,
                              void* d_out, int out_size)
{
    const float* ccs   = (const float*)d_in[0];
    const float* hin   = (const float*)d_in[1];
    const float* pm    = (const float*)d_in[2];
    const float* dlog  = (const float*)d_in[3];
    const float* prim  = (const float*)d_in[4];
    const float* trc   = (const float*)d_in[5];
    const float* sw1   = (const float*)d_in[6];
    const float* sb1   = (const float*)d_in[7];
    const float* sw2   = (const float*)d_in[8];
    const float* sb2   = (const float*)d_in[9];
    const float* mw1   = (const float*)d_in[10];
    const float* mb1   = (const float*)d_in[11];
    const float* mw2   = (const float*)d_in[12];
    const float* mb2   = (const float*)d_in[13];
    const float* modw1 = (const float*)d_in[14];
    const float* modb1 = (const float*)d_in[15];
    const float* modw2 = (const float*)d_in[16];
    const float* modb2 = (const float*)d_in[17];
    const float* nid   = (const float*)d_in[18];
    const int*   conn  = (const int*)d_in[19];
    const int*   bconn = (const int*)d_in[20];
    float* outp = (float*)d_out;

    cudaFuncSetAttribute(cellK2, cudaFuncAttributeMaxDynamicSharedMemorySize, K2_BYTES);
    cudaFuncSetAttribute(cellB_kernel, cudaFuncAttributeMaxDynamicSharedMemorySize, SMEMB_BYTES);

    modk<<<NNN, 256>>>(hin, dlog, prim, trc, modw1, modb1, modw2, modb2, nid);

    cellK2<<<GRID_K2, 192, K2_BYTES>>>(
        ccs, hin, pm, sw1, sb1, sw2, sb2, mw1, mb1, mw2, mb2,
        nid, conn, bconn, outp);

    cellB_kernel<<<512, 512, SMEMB_BYTES>>>(conn, trc, outp);
}